// round 1
// baseline (speedup 1.0000x reference)
#include <cuda_runtime.h>
#include <cuda_bf16.h>
#include <cstdint>
#include <math.h>

#define NROWS 16384
#define NHALF 8192
#define DDIM  256
#define TM 128
#define TN 128
#define NTILES (NROWS / TN)
#define GEMM_THREADS 256
#define SMEM_BYTES (65536 * 2 + 512)

// Scratch (device globals: no allocation allowed)
__device__ __nv_bfloat16 g_zn[NROWS * DDIM];   // normalized rows, bf16 (8 MB)
__device__ float g_pos[NROWS];
__device__ float g_S[NROWS];

// ---------------------------------------------------------------------------
// K1: row L2-normalize, fp32 -> bf16.  One block (64 threads) per row.
// ---------------------------------------------------------------------------
__global__ void norm_kernel(const float* __restrict__ z1,
                            const float* __restrict__ z2) {
    int row = blockIdx.x;
    int t = threadIdx.x;  // 0..63, each handles 4 floats
    const float* src = (row < NHALF) ? (z1 + (size_t)row * DDIM)
                                     : (z2 + (size_t)(row - NHALF) * DDIM);
    float4 v = reinterpret_cast<const float4*>(src)[t];
    float ss = v.x * v.x + v.y * v.y + v.z * v.z + v.w * v.w;
    #pragma unroll
    for (int off = 16; off; off >>= 1)
        ss += __shfl_xor_sync(0xffffffffu, ss, off);
    __shared__ float ws[2];
    if ((t & 31) == 0) ws[t >> 5] = ss;
    __syncthreads();
    float tot = ws[0] + ws[1];
    float inv = 1.0f / fmaxf(sqrtf(tot), 1e-6f);
    __nv_bfloat162 h0 = __floats2bfloat162_rn(v.x * inv, v.y * inv);
    __nv_bfloat162 h1 = __floats2bfloat162_rn(v.z * inv, v.w * inv);
    uint2 packed;
    packed.x = *reinterpret_cast<uint32_t*>(&h0);
    packed.y = *reinterpret_cast<uint32_t*>(&h1);
    reinterpret_cast<uint2*>(g_zn + (size_t)row * DDIM)[t] = packed;
}

// ---------------------------------------------------------------------------
// K2: positives. One warp per row: pos[r] = clip(dot(zn[r], zn[(r+N)%2N]))
// ---------------------------------------------------------------------------
__global__ void pos_kernel() {
    int w = blockIdx.x * (blockDim.x >> 5) + (threadIdx.x >> 5);
    if (w >= NROWS) return;
    int lane = threadIdx.x & 31;
    int p = (w < NHALF) ? (w + NHALF) : (w - NHALF);
    const uint4* A = reinterpret_cast<const uint4*>(g_zn + (size_t)w * DDIM);
    const uint4* B = reinterpret_cast<const uint4*>(g_zn + (size_t)p * DDIM);
    uint4 va = A[lane];
    uint4 vb = B[lane];
    const uint32_t* pa = reinterpret_cast<const uint32_t*>(&va);
    const uint32_t* pb = reinterpret_cast<const uint32_t*>(&vb);
    float dot = 0.f;
    #pragma unroll
    for (int i = 0; i < 4; i++) {
        float2 fa = __bfloat1622float2(*reinterpret_cast<const __nv_bfloat162*>(&pa[i]));
        float2 fb = __bfloat1622float2(*reinterpret_cast<const __nv_bfloat162*>(&pb[i]));
        dot = fmaf(fa.x, fb.x, dot);
        dot = fmaf(fa.y, fb.y, dot);
    }
    #pragma unroll
    for (int off = 16; off; off >>= 1)
        dot += __shfl_xor_sync(0xffffffffu, dot, off);
    if (lane == 0)
        g_pos[w] = fminf(fmaxf(dot, -1.0f + 1e-6f), 1.0f - 1e-6f);
}

// ---------------------------------------------------------------------------
// K3: fused GEMM (Zn @ Zn^T) + per-row sum of exp(10*sim - 10), diag masked.
// 128x128 output tiles, 8 warps (4x2), mma.sync m16n8k16 bf16.
// SMEM tiles row-major [128][256] bf16 with 16B-chunk XOR swizzle
// (chunk' = chunk ^ (row & 7)) -> conflict-free ldmatrix.
// ---------------------------------------------------------------------------
__device__ __forceinline__ void ldsm_x4(uint32_t& r0, uint32_t& r1,
                                        uint32_t& r2, uint32_t& r3,
                                        uint32_t addr) {
    asm volatile("ldmatrix.sync.aligned.m8n8.x4.shared.b16 {%0,%1,%2,%3}, [%4];"
                 : "=r"(r0), "=r"(r1), "=r"(r2), "=r"(r3)
                 : "r"(addr));
}

__device__ __forceinline__ void mma16816(float* d, const uint32_t* a,
                                         uint32_t b0, uint32_t b1) {
    asm volatile(
        "mma.sync.aligned.m16n8k16.row.col.f32.bf16.bf16.f32 "
        "{%0,%1,%2,%3}, {%4,%5,%6,%7}, {%8,%9}, {%0,%1,%2,%3};"
        : "+f"(d[0]), "+f"(d[1]), "+f"(d[2]), "+f"(d[3])
        : "r"(a[0]), "r"(a[1]), "r"(a[2]), "r"(a[3]), "r"(b0), "r"(b1));
}

__device__ __forceinline__ float ex2f(float x) {
    float y;
    asm("ex2.approx.f32 %0, %1;" : "=f"(y) : "f"(x));
    return y;
}

template <bool DIAG>
__device__ __forceinline__ void epilogue(float (&acc)[2][8][4],
                                         float (&rsum)[2][2],
                                         int rowb, int colb) {
    const float C1 = 14.42695040888963f;  // 10 * log2(e)
    #pragma unroll
    for (int mf = 0; mf < 2; ++mf)
        #pragma unroll
        for (int nf = 0; nf < 8; ++nf)
            #pragma unroll
            for (int e = 0; e < 4; ++e) {
                // exp(10*sim - 10) = 2^(sim*C1 - C1)
                float y = fmaf(acc[mf][nf][e], C1, -C1);
                float ev = ex2f(y);
                if (DIAG) {
                    int row = rowb + mf * 16 + ((e >> 1) << 3);
                    int col = colb + nf * 8 + (e & 1);
                    if (row == col) ev = 0.f;
                }
                rsum[mf][e >> 1] += ev;
                acc[mf][nf][e] = 0.f;
            }
}

__global__ __launch_bounds__(GEMM_THREADS, 1)
void gemm_lse_kernel() {
    extern __shared__ char smem[];
    char* sA = smem;
    char* sB = smem + 65536;
    float* s_rowsum = reinterpret_cast<float*>(smem + 131072);

    const int tid = threadIdx.x;
    const int lane = tid & 31;
    const int wid = tid >> 5;
    const int warp_m = wid & 3;   // 4 warps along M
    const int warp_n = wid >> 2;  // 2 warps along N
    const int bx = blockIdx.x;

    uint32_t sA_u = (uint32_t)__cvta_generic_to_shared(sA);
    uint32_t sB_u = (uint32_t)__cvta_generic_to_shared(sB);

    if (tid < TM) s_rowsum[tid] = 0.f;

    // ---- Load A tile (rows bx*128 .. +128) into swizzled smem ----
    {
        const uint4* gp = reinterpret_cast<const uint4*>(g_zn) + (size_t)bx * TM * 32;
        #pragma unroll 4
        for (int i = tid; i < TM * 32; i += GEMM_THREADS) {
            int r = i >> 5, c = i & 31;
            uint4 v = gp[i];
            *reinterpret_cast<uint4*>(sA + r * 512 + ((c ^ (r & 7)) << 4)) = v;
        }
    }

    // Fragment lane constants
    const int aRow = lane & 15;
    const int aSel = lane >> 4;
    const int bRowOff = (lane & 7) + ((lane >> 4) << 3);
    const int bSel = (lane >> 3) & 1;
    const int g = lane >> 2;
    const int q = lane & 3;

    uint32_t aAddrBase[2];
    #pragma unroll
    for (int mf = 0; mf < 2; mf++)
        aAddrBase[mf] = sA_u + (warp_m * 32 + mf * 16 + aRow) * 512;
    const int aR7 = aRow & 7;

    uint32_t bAddrBase[4];
    #pragma unroll
    for (int p = 0; p < 4; p++)
        bAddrBase[p] = sB_u + (warp_n * 64 + p * 16 + bRowOff) * 512;
    const int bR7 = bRowOff & 7;

    float acc[2][8][4];
    #pragma unroll
    for (int mf = 0; mf < 2; ++mf)
        #pragma unroll
        for (int nf = 0; nf < 8; ++nf)
            #pragma unroll
            for (int e = 0; e < 4; ++e) acc[mf][nf][e] = 0.f;

    float rsum[2][2] = {{0.f, 0.f}, {0.f, 0.f}};

    const int rowb = bx * TM + warp_m * 32 + g;

    for (int jt = 0; jt < NTILES; ++jt) {
        __syncthreads();  // previous tile fully consumed
        // ---- Load B tile (rows jt*128 .. +128) ----
        {
            const uint4* gp = reinterpret_cast<const uint4*>(g_zn) + (size_t)jt * TN * 32;
            #pragma unroll 4
            for (int i = tid; i < TN * 32; i += GEMM_THREADS) {
                int r = i >> 5, c = i & 31;
                uint4 v = gp[i];
                *reinterpret_cast<uint4*>(sB + r * 512 + ((c ^ (r & 7)) << 4)) = v;
            }
        }
        __syncthreads();

        // ---- MMA mainloop over K = 256 (16 k16 steps) ----
        #pragma unroll
        for (int kk = 0; kk < 16; ++kk) {
            uint32_t a[2][4], b[4][4];
            uint32_t aoff = (uint32_t)(((2 * kk + aSel) ^ aR7) << 4);
            ldsm_x4(a[0][0], a[0][1], a[0][2], a[0][3], aAddrBase[0] + aoff);
            ldsm_x4(a[1][0], a[1][1], a[1][2], a[1][3], aAddrBase[1] + aoff);
            uint32_t boff = (uint32_t)(((2 * kk + bSel) ^ bR7) << 4);
            #pragma unroll
            for (int p = 0; p < 4; p++)
                ldsm_x4(b[p][0], b[p][1], b[p][2], b[p][3], bAddrBase[p] + boff);
            #pragma unroll
            for (int mf = 0; mf < 2; ++mf)
                #pragma unroll
                for (int nf = 0; nf < 8; ++nf)
                    mma16816(acc[mf][nf], a[mf],
                             b[nf >> 1][(nf & 1) * 2],
                             b[nf >> 1][(nf & 1) * 2 + 1]);
        }

        // ---- Epilogue: exp + row-sum accumulate (mask diag in own tile) ----
        int colb = jt * TN + warp_n * 64 + q * 2;
        if (jt == bx)
            epilogue<true>(acc, rsum, rowb, colb);
        else
            epilogue<false>(acc, rsum, rowb, colb);
    }

    // ---- Reduce row sums: quad shuffle, then cross-warp via smem atomics ----
    #pragma unroll
    for (int mf = 0; mf < 2; ++mf)
        #pragma unroll
        for (int h = 0; h < 2; ++h) {
            float v = rsum[mf][h];
            v += __shfl_xor_sync(0xffffffffu, v, 1);
            v += __shfl_xor_sync(0xffffffffu, v, 2);
            if (q == 0)
                atomicAdd(&s_rowsum[warp_m * 32 + mf * 16 + h * 8 + g], v);
        }
    __syncthreads();
    if (tid < TM) g_S[bx * TM + tid] = s_rowsum[tid];
}

// ---------------------------------------------------------------------------
// K4: loss = mean(-10*pos + 10 + log(S))
// ---------------------------------------------------------------------------
__global__ void loss_kernel(float* __restrict__ out) {
    __shared__ double sred[256];
    double acc = 0.0;
    for (int i = threadIdx.x; i < NROWS; i += 256)
        acc += (double)logf(g_S[i]) + 10.0 - 10.0 * (double)g_pos[i];
    sred[threadIdx.x] = acc;
    __syncthreads();
    for (int s = 128; s; s >>= 1) {
        if (threadIdx.x < s) sred[threadIdx.x] += sred[threadIdx.x + s];
        __syncthreads();
    }
    if (threadIdx.x == 0) out[0] = (float)(sred[0] / (double)NROWS);
}

// ---------------------------------------------------------------------------
extern "C" void kernel_launch(void* const* d_in, const int* in_sizes, int n_in,
                              void* d_out, int out_size) {
    (void)in_sizes; (void)n_in; (void)out_size;
    const float* z1 = (const float*)d_in[0];
    const float* z2 = (const float*)d_in[1];
    float* out = (float*)d_out;

    cudaFuncSetAttribute(gemm_lse_kernel,
                         cudaFuncAttributeMaxDynamicSharedMemorySize, SMEM_BYTES);

    norm_kernel<<<NROWS, 64>>>(z1, z2);
    pos_kernel<<<NROWS / 8, 256>>>();
    gemm_lse_kernel<<<NTILES, GEMM_THREADS, SMEM_BYTES>>>();
    loss_kernel<<<1, 256>>>(out);
}

// round 3
// speedup vs baseline: 1.8158x; 1.8158x over previous
#include <cuda_runtime.h>
#include <cuda_bf16.h>
#include <cstdint>
#include <math.h>

#define NROWS 16384
#define NHALF 8192
#define DDIM  256
#define TM    128
#define NT    128          // tiles per dimension
#define GT    256          // gemm threads
#define GRID_SYM 1088      // sum_{bi} ceil((128-bi)/8)

// ---- device scratch (no allocation allowed) ----
__device__ __nv_bfloat16 g_zn[NROWS * DDIM];   // normalized rows (8 MB)
__device__ float  g_pos[NROWS];
__device__ float  g_S[NROWS];
__device__ double g_part[64];

// ---- smem layout for gemm kernel ----
#define OFF_A    0
#define OFF_B0   65536
#define OFF_B1   131072
#define OFF_SROW 196608    // float[128]
#define OFF_SCOL 197120    // float[128]
#define SMEM_TOTAL 197632

// ============================ helpers ============================
__device__ __forceinline__ uint32_t smem_u32(const void* p) {
    uint32_t a;
    asm("{ .reg .u64 t; cvta.to.shared.u64 t, %1; cvt.u32.u64 %0, t; }"
        : "=r"(a) : "l"(p));
    return a;
}
__device__ __forceinline__ void ldsm_x4(uint32_t& r0, uint32_t& r1,
                                        uint32_t& r2, uint32_t& r3,
                                        uint32_t addr) {
    asm volatile("ldmatrix.sync.aligned.m8n8.x4.shared.b16 {%0,%1,%2,%3}, [%4];"
                 : "=r"(r0), "=r"(r1), "=r"(r2), "=r"(r3) : "r"(addr));
}
__device__ __forceinline__ void mma16816(float* d, const uint32_t* a,
                                         uint32_t b0, uint32_t b1) {
    asm volatile(
        "mma.sync.aligned.m16n8k16.row.col.f32.bf16.bf16.f32 "
        "{%0,%1,%2,%3}, {%4,%5,%6,%7}, {%8,%9}, {%0,%1,%2,%3};"
        : "+f"(d[0]), "+f"(d[1]), "+f"(d[2]), "+f"(d[3])
        : "r"(a[0]), "r"(a[1]), "r"(a[2]), "r"(a[3]), "r"(b0), "r"(b1));
}
__device__ __forceinline__ float ex2f(float x) {
    float y; asm("ex2.approx.f32 %0, %1;" : "=f"(y) : "f"(x)); return y;
}
__device__ __forceinline__ void cp_commit() {
    asm volatile("cp.async.commit_group;" ::: "memory");
}
__device__ __forceinline__ void cp_wait0() {
    asm volatile("cp.async.wait_group 0;" ::: "memory");
}
// cp.async a 128x256 bf16 row-strip into swizzled smem tile
__device__ __forceinline__ void cp_tile(uint32_t sdst, int rowblk, int tid) {
    const char* gp = reinterpret_cast<const char*>(g_zn) + (size_t)rowblk * (TM * 512);
    #pragma unroll
    for (int it = 0; it < 16; ++it) {
        int c = tid + it * GT;            // 16B chunk index 0..4095
        int r = c >> 5, cc = c & 31;
        uint32_t d = sdst + r * 512 + (((cc ^ (r & 7))) << 4);
        asm volatile("cp.async.cg.shared.global [%0], [%1], 16;"
                     :: "r"(d), "l"(gp + (size_t)c * 16) : "memory");
    }
}

// ============================ K1: normalize ============================
__global__ void norm_kernel(const float* __restrict__ z1,
                            const float* __restrict__ z2) {
    int row = blockIdx.x;
    int t = threadIdx.x;  // 0..63
    const float* src = (row < NHALF) ? (z1 + (size_t)row * DDIM)
                                     : (z2 + (size_t)(row - NHALF) * DDIM);
    float4 v = reinterpret_cast<const float4*>(src)[t];
    float ss = v.x * v.x + v.y * v.y + v.z * v.z + v.w * v.w;
    #pragma unroll
    for (int o = 16; o; o >>= 1) ss += __shfl_xor_sync(0xffffffffu, ss, o);
    __shared__ float ws[2];
    if ((t & 31) == 0) ws[t >> 5] = ss;
    __syncthreads();
    float inv = 1.0f / fmaxf(sqrtf(ws[0] + ws[1]), 1e-6f);
    __nv_bfloat162 h0 = __floats2bfloat162_rn(v.x * inv, v.y * inv);
    __nv_bfloat162 h1 = __floats2bfloat162_rn(v.z * inv, v.w * inv);
    uint2 packed;
    packed.x = *reinterpret_cast<uint32_t*>(&h0);
    packed.y = *reinterpret_cast<uint32_t*>(&h1);
    reinterpret_cast<uint2*>(g_zn + (size_t)row * DDIM)[t] = packed;
}

// ============================ K2: positives + zero g_S ============================
__global__ void pos_kernel() {
    int w = blockIdx.x * (blockDim.x >> 5) + (threadIdx.x >> 5);
    if (w >= NROWS) return;
    int lane = threadIdx.x & 31;
    int p = (w < NHALF) ? (w + NHALF) : (w - NHALF);
    uint4 va = reinterpret_cast<const uint4*>(g_zn + (size_t)w * DDIM)[lane];
    uint4 vb = reinterpret_cast<const uint4*>(g_zn + (size_t)p * DDIM)[lane];
    const uint32_t* pa = reinterpret_cast<const uint32_t*>(&va);
    const uint32_t* pb = reinterpret_cast<const uint32_t*>(&vb);
    float dot = 0.f;
    #pragma unroll
    for (int i = 0; i < 4; i++) {
        float2 fa = __bfloat1622float2(*reinterpret_cast<const __nv_bfloat162*>(&pa[i]));
        float2 fb = __bfloat1622float2(*reinterpret_cast<const __nv_bfloat162*>(&pb[i]));
        dot = fmaf(fa.x, fb.x, dot);
        dot = fmaf(fa.y, fb.y, dot);
    }
    #pragma unroll
    for (int o = 16; o; o >>= 1) dot += __shfl_xor_sync(0xffffffffu, dot, o);
    if (lane == 0) {
        g_pos[w] = fminf(fmaxf(dot, -1.0f + 1e-6f), 1.0f - 1e-6f);
        g_S[w] = 0.f;
    }
}

// ===================== K3: symmetric GEMM + exp-sum fusion =====================
template <bool DIAG>
__device__ __forceinline__ void epilogue_sym(float (&acc)[2][8][4],
                                             float (&rsum)[2][2],
                                             float* scol, int lane,
                                             int warp_m, int warp_n) {
    const float C1 = 14.42695040888963f;  // 10*log2(e)
    const int g = lane >> 2, q = lane & 3;
    float csum[8][2];
    #pragma unroll
    for (int nf = 0; nf < 8; ++nf) { csum[nf][0] = 0.f; csum[nf][1] = 0.f; }
    #pragma unroll
    for (int mf = 0; mf < 2; ++mf)
        #pragma unroll
        for (int nf = 0; nf < 8; ++nf)
            #pragma unroll
            for (int e = 0; e < 4; ++e) {
                float ev = ex2f(fmaf(acc[mf][nf][e], C1, -C1));
                if (DIAG) {
                    int row = warp_m * 32 + mf * 16 + ((e >> 1) << 3) + g;
                    int col = warp_n * 64 + nf * 8 + q * 2 + (e & 1);
                    if (row == col) ev = 0.f;
                }
                rsum[mf][e >> 1] += ev;
                csum[nf][e & 1] += ev;
                acc[mf][nf][e] = 0.f;
            }
    if (!DIAG) {
        #pragma unroll
        for (int nf = 0; nf < 8; ++nf)
            #pragma unroll
            for (int e1 = 0; e1 < 2; ++e1) {
                float v = csum[nf][e1];
                v += __shfl_xor_sync(0xffffffffu, v, 4);
                v += __shfl_xor_sync(0xffffffffu, v, 8);
                v += __shfl_xor_sync(0xffffffffu, v, 16);
                if (g == 0)
                    atomicAdd(&scol[warp_n * 64 + nf * 8 + q * 2 + e1], v);
            }
    }
}

__global__ void __launch_bounds__(GT, 1) gemm_sym_kernel() {
    extern __shared__ char smem[];
    const int tid = threadIdx.x, lane = tid & 31, wid = tid >> 5;
    const int warp_m = wid & 3, warp_n = wid >> 2;
    uint32_t sb = smem_u32(smem);
    float* srow = reinterpret_cast<float*>(smem + OFF_SROW);
    float* scol = reinterpret_cast<float*>(smem + OFF_SCOL);

    // map blockIdx -> (bi, j0, len): chunks of 8 j-tiles per row-block
    int idx = blockIdx.x, bi = 0;
    for (;;) {
        int nc = (NT - bi + 7) >> 3;
        if (idx < nc) break;
        idx -= nc; ++bi;
    }
    const int j0 = bi + idx * 8;
    const int len = min(8, NT - j0);

    if (tid < TM) srow[tid] = 0.f;

    cp_tile(sb + OFF_A, bi, tid);
    cp_tile(sb + OFF_B0, j0, tid);
    cp_commit();

    // fragment lane constants (identical to proven round-1 scheme)
    const int aRow = lane & 15;
    const int aSel = lane >> 4;
    const int bRowOff = (lane & 7) + ((lane >> 4) << 3);
    const int bSel = (lane >> 3) & 1;

    uint32_t aAddrBase[2];
    #pragma unroll
    for (int mf = 0; mf < 2; mf++)
        aAddrBase[mf] = sb + OFF_A + (warp_m * 32 + mf * 16 + aRow) * 512;
    const int aR7 = aRow & 7;

    uint32_t bAddrBase0[4];
    #pragma unroll
    for (int p = 0; p < 4; p++)
        bAddrBase0[p] = sb + OFF_B0 + (warp_n * 64 + p * 16 + bRowOff) * 512;
    const int bR7 = bRowOff & 7;

    float acc[2][8][4];
    #pragma unroll
    for (int mf = 0; mf < 2; ++mf)
        #pragma unroll
        for (int nf = 0; nf < 8; ++nf)
            #pragma unroll
            for (int e = 0; e < 4; ++e) acc[mf][nf][e] = 0.f;
    float rsum[2][2] = {{0.f, 0.f}, {0.f, 0.f}};

    cp_wait0();
    __syncthreads();

    for (int t = 0; t < len; ++t) {
        const int buf = t & 1;
        if (t + 1 < len) {
            cp_tile(sb + (buf ? OFF_B0 : OFF_B1), j0 + t + 1, tid);
            cp_commit();
        }
        const uint32_t bofs = (uint32_t)buf * 65536u;

        // ---- MMA over K = 256 ----
        #pragma unroll
        for (int kk = 0; kk < 16; ++kk) {
            uint32_t a[2][4], b[4][4];
            uint32_t aoff = (uint32_t)(((2 * kk + aSel) ^ aR7) << 4);
            ldsm_x4(a[0][0], a[0][1], a[0][2], a[0][3], aAddrBase[0] + aoff);
            ldsm_x4(a[1][0], a[1][1], a[1][2], a[1][3], aAddrBase[1] + aoff);
            uint32_t boff = (uint32_t)(((2 * kk + bSel) ^ bR7) << 4) + bofs;
            #pragma unroll
            for (int p = 0; p < 4; p++)
                ldsm_x4(b[p][0], b[p][1], b[p][2], b[p][3], bAddrBase0[p] + boff);
            #pragma unroll
            for (int mf = 0; mf < 2; ++mf)
                #pragma unroll
                for (int nf = 0; nf < 8; ++nf)
                    mma16816(acc[mf][nf], a[mf],
                             b[nf >> 1][(nf & 1) * 2],
                             b[nf >> 1][(nf & 1) * 2 + 1]);
        }

        // ---- epilogue: exp + row-sum (regs) + col-sum (smem) ----
        const bool diag = (j0 + t == bi);
        if (tid < TM) scol[tid] = 0.f;
        __syncthreads();
        if (diag) epilogue_sym<true >(acc, rsum, scol, lane, warp_m, warp_n);
        else      epilogue_sym<false>(acc, rsum, scol, lane, warp_m, warp_n);
        __syncthreads();
        if (!diag && tid < TM)
            atomicAdd(&g_S[(j0 + t) * TM + tid], scol[tid]);

        cp_wait0();
        __syncthreads();
    }

    // ---- row sums -> smem -> one global atomic per row ----
    const int g = lane >> 2, q = lane & 3;
    #pragma unroll
    for (int mf = 0; mf < 2; ++mf)
        #pragma unroll
        for (int h = 0; h < 2; ++h) {
            float v = rsum[mf][h];
            v += __shfl_xor_sync(0xffffffffu, v, 1);
            v += __shfl_xor_sync(0xffffffffu, v, 2);
            if (q == 0)
                atomicAdd(&srow[warp_m * 32 + mf * 16 + h * 8 + g], v);
        }
    __syncthreads();
    if (tid < TM) atomicAdd(&g_S[bi * TM + tid], srow[tid]);
}

// ============================ K4: loss reduce ============================
__global__ void loss_partial_kernel() {
    int r = blockIdx.x * 256 + threadIdx.x;
    double v = (double)logf(g_S[r]) + 10.0 - 10.0 * (double)g_pos[r];
    #pragma unroll
    for (int o = 16; o; o >>= 1) v += __shfl_xor_sync(0xffffffffu, v, o);
    __shared__ double sd[8];
    if ((threadIdx.x & 31) == 0) sd[threadIdx.x >> 5] = v;
    __syncthreads();
    if (threadIdx.x == 0) {
        double a = 0.0;
        #pragma unroll
        for (int i = 0; i < 8; ++i) a += sd[i];
        g_part[blockIdx.x] = a;
    }
}
__global__ void loss_final_kernel(float* __restrict__ out) {
    int lane = threadIdx.x;  // 32 threads
    double a = g_part[lane] + g_part[lane + 32];
    #pragma unroll
    for (int o = 16; o; o >>= 1) a += __shfl_xor_sync(0xffffffffu, a, o);
    if (lane == 0) out[0] = (float)(a / (double)NROWS);
}

// ---------------------------------------------------------------------------
extern "C" void kernel_launch(void* const* d_in, const int* in_sizes, int n_in,
                              void* d_out, int out_size) {
    (void)in_sizes; (void)n_in; (void)out_size;
    const float* z1 = (const float*)d_in[0];
    const float* z2 = (const float*)d_in[1];
    float* out = (float*)d_out;

    cudaFuncSetAttribute(gemm_sym_kernel,
                         cudaFuncAttributeMaxDynamicSharedMemorySize, SMEM_TOTAL);

    norm_kernel<<<NROWS, 64>>>(z1, z2);
    pos_kernel<<<NROWS / 8, 256>>>();
    gemm_sym_kernel<<<GRID_SYM, GT, SMEM_TOTAL>>>();
    loss_partial_kernel<<<64, 256>>>();
    loss_final_kernel<<<1, 32>>>(out);
}